// round 1
// baseline (speedup 1.0000x reference)
#include <cuda_runtime.h>
#include <math.h>

#define H        128
#define STRIDE   132      // 132 % 32 == 4 -> conflict-free row AND column smem access
#define NCTA     128
#define NTHREADS 256
#define MAXIT    500
#define TOLF     1e-3f

__device__ unsigned g_count;          // grid-barrier arrival counter (zeroed per launch)
__device__ float    g_res[MAXIT];     // per-iteration residual accumulators

struct __align__(16) Smem {
    float Wy0[H * STRIDE];
    float Wy1[H * STRIDE];
    float W1p[H * STRIDE];
    float yv0[2][H];
    float yv1[2][H];
    float zz [2][H];
    float v2 [2][H];
    float v1 [2][H];
    float part1[2][2][H];   // [half][sample][h]
    float part2[2][2][H];
    float xbuf[2][H];
    float ubuf[2][H];
    float red[2][4];
    float bcast;
};

__global__ void pblnn_init_kernel() {
    int t = blockIdx.x * blockDim.x + threadIdx.x;
    if (t == 0) g_count = 0u;
    if (t < MAXIT) g_res[t] = 0.f;
}

__device__ __forceinline__ float softplus_f(float s) {
    float e = __expf(s);
    float z = __logf(1.f + e);
    return (s > 15.f) ? s : z;
}

__device__ __forceinline__ void spsig(float s, float& z, float& sg) {
    float e = __expf(s);
    float zz_ = __logf(1.f + e);
    float sgg = e / (1.f + e);
    if (s > 15.f) { zz_ = s; sgg = 1.f; }
    z = zz_; sg = sgg;
}

// dual-sample dot of smem vectors against a global weight row
__device__ __forceinline__ void dot2(const float* xs0, const float* xs1,
                                     const float* __restrict__ w,
                                     float& d0, float& d1) {
    float a0 = 0.f, a1 = 0.f;
#pragma unroll 16
    for (int j = 0; j < H; j++) {
        float wv = __ldg(&w[j]);
        a0 += xs0[j] * wv;
        a1 += xs1[j] * wv;
    }
    d0 = a0; d1 = a1;
}

__global__ __launch_bounds__(NTHREADS, 1)
void pblnn_kernel(
    const float* __restrict__ x,      const float* __restrict__ y,
    const float* __restrict__ wuu0_w, const float* __restrict__ wuu0_b,
    const float* __restrict__ wyu0_w, const float* __restrict__ wyu0_b,
    const float* __restrict__ wy0,
    const float* __restrict__ wu0_w,  const float* __restrict__ wu0_b,
    const float* __restrict__ wuu1_w, const float* __restrict__ wuu1_b,
    const float* __restrict__ wzu1_w, const float* __restrict__ wzu1_b,
    const float* __restrict__ wz1,
    const float* __restrict__ wyu1_w, const float* __restrict__ wyu1_b,
    const float* __restrict__ wy1,
    const float* __restrict__ wu1_w,  const float* __restrict__ wu1_b,
    const float* __restrict__ wzu2_w, const float* __restrict__ wzu2_b,
    const float* __restrict__ wz2,
    const float* __restrict__ wyu2_w, const float* __restrict__ wyu2_b,
    const float* __restrict__ wy2,
    float* __restrict__ out)
{
    extern __shared__ char smem_raw[];
    Smem& S = *reinterpret_cast<Smem*>(smem_raw);

    const int tid  = threadIdx.x;
    const int h    = tid & (H - 1);
    const int half = tid >> 7;
    const int j0   = half * 64;
    const int samp = blockIdx.x * 2;

    // ---- load x (2 samples), weight matrices into smem (stride-132 padded) ----
    for (int e = tid; e < 2 * H; e += NTHREADS)
        S.xbuf[e >> 7][e & 127] = x[samp * H + e];
    for (int e = tid; e < H * H; e += NTHREADS) {
        int r = e >> 7, c = e & 127;
        S.Wy0[r * STRIDE + c] = wy0[e];
        S.Wy1[r * STRIDE + c] = wy1[e];
        S.W1p[r * STRIDE + c] = fmaxf(wz1[e], 0.f);
    }
    __syncthreads();

    const float* xs0 = S.xbuf[0];
    const float* xs1 = S.xbuf[1];

    // ---- y-independent precompute (once) ----
    float t0, t1;
    dot2(xs0, xs1, &wuu0_w[h * H], t0, t1);
    float u0_0 = softplus_f(t0 + wuu0_b[h]);
    float u0_1 = softplus_f(t1 + wuu0_b[h]);

    float a0r0, a0r1; dot2(xs0, xs1, &wyu0_w[h * H], a0r0, a0r1);
    a0r0 += wyu0_b[h]; a0r1 += wyu0_b[h];
    float c0r0, c0r1; dot2(xs0, xs1, &wu0_w[h * H], c0r0, c0r1);
    c0r0 += wu0_b[h]; c0r1 += wu0_b[h];

    if (half == 0) { S.ubuf[0][h] = u0_0; S.ubuf[1][h] = u0_1; }
    __syncthreads();

    const float* us0 = S.ubuf[0];
    const float* us1 = S.ubuf[1];

    float u1_0, u1_1; dot2(us0, us1, &wuu1_w[h * H], u1_0, u1_1);
    u1_0 = softplus_f(u1_0 + wuu1_b[h]);
    u1_1 = softplus_f(u1_1 + wuu1_b[h]);
    float zur0, zur1; dot2(us0, us1, &wzu1_w[h * H], zur0, zur1);
    zur0 = softplus_f(zur0 + wzu1_b[h]);
    zur1 = softplus_f(zur1 + wzu1_b[h]);
    float a1r0, a1r1; dot2(us0, us1, &wyu1_w[h * H], a1r0, a1r1);
    a1r0 += wyu1_b[h]; a1r1 += wyu1_b[h];
    float c1r0, c1r1; dot2(us0, us1, &wu1_w[h * H], c1r0, c1r1);
    c1r0 += wu1_b[h]; c1r1 += wu1_b[h];

    __syncthreads();     // everyone done reading u0
    if (half == 0) { S.ubuf[0][h] = u1_0; S.ubuf[1][h] = u1_1; }
    __syncthreads();

    float a2r0, a2r1; dot2(us0, us1, &wyu2_w[h * H], a2r0, a2r1);
    float wy2h = wy2[h];
    float a2w0 = (a2r0 + wyu2_b[h]) * wy2h;
    float a2w1 = (a2r1 + wyu2_b[h]) * wy2h;

    float zt0, zt1; dot2(us0, us1, wzu2_w, zt0, zt1);
    float zu2_0 = softplus_f(zt0 + wzu2_b[0]);
    float zu2_1 = softplus_f(zt1 + wzu2_b[0]);
    float w2pr  = fmaxf(wz2[h], 0.f);
    float vw2_0 = zu2_0 * w2pr;       // v2 = vw2 * sigmoid(s2)
    float vw2_1 = zu2_1 * w2pr;

    float yr0 = y[samp * H + h];
    float yr1 = y[(samp + 1) * H + h];
    float y1r0 = 1.f, y1r1 = 1.f;

    const float inv256 = 1.f / 256.f;

    // ---- fixed-point iterations ----
    for (int it = 0; it < MAXIT; ++it) {
        if (half == 0) {
            S.yv0[0][h] = y1r0 * a0r0;  S.yv0[1][h] = y1r1 * a0r1;
            S.yv1[0][h] = y1r0 * a1r0;  S.yv1[1][h] = y1r1 * a1r1;
        }
        __syncthreads();

        // M1: s1[h] partial = sum_j yv0[j] * Wy0[h][j]
        {
            const float4* w  = (const float4*)&S.Wy0[h * STRIDE + j0];
            const float4* p0 = (const float4*)&S.yv0[0][j0];
            const float4* p1 = (const float4*)&S.yv0[1][j0];
            float a0 = 0.f, a1 = 0.f;
#pragma unroll
            for (int q = 0; q < 16; q++) {
                float4 ww = w[q], v0 = p0[q], v1 = p1[q];
                a0 += ww.x * v0.x + ww.y * v0.y + ww.z * v0.z + ww.w * v0.w;
                a1 += ww.x * v1.x + ww.y * v1.y + ww.z * v1.z + ww.w * v1.w;
            }
            S.part1[half][0][h] = a0;  S.part1[half][1][h] = a1;
        }
        __syncthreads();

        float s1_0 = S.part1[0][0][h] + S.part1[1][0][h] + c0r0;
        float s1_1 = S.part1[0][1][h] + S.part1[1][1][h] + c0r1;
        float z1_0, sg1_0, z1_1, sg1_1;
        spsig(s1_0, z1_0, sg1_0);
        spsig(s1_1, z1_1, sg1_1);
        float zs1r0 = sg1_0 * zur0, zs1r1 = sg1_1 * zur1;
        if (half == 0) { S.zz[0][h] = z1_0 * zur0;  S.zz[1][h] = z1_1 * zur1; }
        __syncthreads();

        // M2: s2[h] partial = sum_k zz[k]*W1p[h][k] + sum_j yv1[j]*Wy1[h][j]
        {
            const float4* wA = (const float4*)&S.W1p[h * STRIDE + j0];
            const float4* wB = (const float4*)&S.Wy1[h * STRIDE + j0];
            const float4* za = (const float4*)&S.zz[0][j0];
            const float4* zb = (const float4*)&S.zz[1][j0];
            const float4* va = (const float4*)&S.yv1[0][j0];
            const float4* vb = (const float4*)&S.yv1[1][j0];
            float a0 = 0.f, a1 = 0.f;
#pragma unroll
            for (int q = 0; q < 16; q++) {
                float4 A = wA[q], Bm = wB[q];
                float4 z0 = za[q], z1q = zb[q], v0 = va[q], v1 = vb[q];
                a0 += A.x * z0.x + A.y * z0.y + A.z * z0.z + A.w * z0.w
                    + Bm.x * v0.x + Bm.y * v0.y + Bm.z * v0.z + Bm.w * v0.w;
                a1 += A.x * z1q.x + A.y * z1q.y + A.z * z1q.z + A.w * z1q.w
                    + Bm.x * v1.x + Bm.y * v1.y + Bm.z * v1.z + Bm.w * v1.w;
            }
            S.part1[half][0][h] = a0;  S.part1[half][1][h] = a1;
        }
        __syncthreads();

        float s2_0 = S.part1[0][0][h] + S.part1[1][0][h] + c1r0;
        float s2_1 = S.part1[0][1][h] + S.part1[1][1][h] + c1r1;
        float sg2_0 = 1.f / (1.f + __expf(-s2_0));
        float sg2_1 = 1.f / (1.f + __expf(-s2_1));
        if (half == 0) { S.v2[0][h] = vw2_0 * sg2_0;  S.v2[1][h] = vw2_1 * sg2_1; }
        __syncthreads();

        // M3 (t[k] = sum_h v2[h]*W1p[h][k]) + M4a (gA[j] = sum_h v2[h]*Wy1[h][j]) fused
        {
            float tA0 = 0.f, tA1 = 0.f, gAp0 = 0.f, gAp1 = 0.f;
#pragma unroll
            for (int q = 0; q < 16; q++) {
                int hp = j0 + 4 * q;
                float4 v20 = *(const float4*)&S.v2[0][hp];
                float4 v21 = *(const float4*)&S.v2[1][hp];
#define STEP3(r, c0v, c1v) { \
                float vA = S.W1p[(hp + r) * STRIDE + h]; \
                float vB = S.Wy1[(hp + r) * STRIDE + h]; \
                tA0  += (c0v) * vA;  tA1  += (c1v) * vA; \
                gAp0 += (c0v) * vB;  gAp1 += (c1v) * vB; }
                STEP3(0, v20.x, v21.x)
                STEP3(1, v20.y, v21.y)
                STEP3(2, v20.z, v21.z)
                STEP3(3, v20.w, v21.w)
#undef STEP3
            }
            S.part1[half][0][h] = tA0;   S.part1[half][1][h] = tA1;
            S.part2[half][0][h] = gAp0;  S.part2[half][1][h] = gAp1;
        }
        __syncthreads();

        float tv0 = S.part1[0][0][h] + S.part1[1][0][h];
        float tv1 = S.part1[0][1][h] + S.part1[1][1][h];
        float gA0 = S.part2[0][0][h] + S.part2[1][0][h];
        float gA1 = S.part2[0][1][h] + S.part2[1][1][h];
        if (half == 0) { S.v1[0][h] = tv0 * zs1r0;  S.v1[1][h] = tv1 * zs1r1; }
        __syncthreads();

        // M4b: gB[j] = sum_k v1[k]*Wy0[k][j]
        {
            float gBp0 = 0.f, gBp1 = 0.f;
#pragma unroll
            for (int q = 0; q < 16; q++) {
                int kp = j0 + 4 * q;
                float4 v10 = *(const float4*)&S.v1[0][kp];
                float4 v11 = *(const float4*)&S.v1[1][kp];
#define STEP4(r, c0v, c1v) { \
                float wv = S.Wy0[(kp + r) * STRIDE + h]; \
                gBp0 += (c0v) * wv;  gBp1 += (c1v) * wv; }
                STEP4(0, v10.x, v11.x)
                STEP4(1, v10.y, v11.y)
                STEP4(2, v10.z, v11.z)
                STEP4(3, v10.w, v11.w)
#undef STEP4
            }
            S.part1[half][0][h] = gBp0;  S.part1[half][1][h] = gBp1;
        }
        __syncthreads();

        float gB0 = S.part1[0][0][h] + S.part1[1][0][h];
        float gB1 = S.part1[0][1][h] + S.part1[1][1][h];

        float g0 = a1r0 * gA0 + a0r0 * gB0 + a2w0 + 0.5f * y1r0;
        float g1 = a1r1 * gA1 + a0r1 * gB1 + a2w1 + 0.5f * y1r1;
        float r0 = yr0 - g0, r1 = yr1 - g1;
        float stepi = 4.f / (float)(it + 1);
        y1r0 += stepi * r0;
        y1r1 += stepi * r1;

        // residual: mean over batch of ||y - g||_2 — global reduction + grid barrier
        float q0 = r0 * r0, q1 = r1 * r1;
        if (half == 0) {
#pragma unroll
            for (int o = 16; o; o >>= 1) {
                q0 += __shfl_xor_sync(0xffffffffu, q0, o);
                q1 += __shfl_xor_sync(0xffffffffu, q1, o);
            }
            if ((h & 31) == 0) { S.red[0][h >> 5] = q0;  S.red[1][h >> 5] = q1; }
        }
        __syncthreads();
        if (tid == 0) {
            float ss0 = S.red[0][0] + S.red[0][1] + S.red[0][2] + S.red[0][3];
            float ss1 = S.red[1][0] + S.red[1][1] + S.red[1][2] + S.red[1][3];
            atomicAdd(&g_res[it], sqrtf(ss0) + sqrtf(ss1));
            __threadfence();
            atomicAdd(&g_count, 1u);
            unsigned tgt = (unsigned)(it + 1) * (unsigned)gridDim.x;
            while (*((volatile unsigned*)&g_count) < tgt) { }
            __threadfence();
            S.bcast = g_res[it];
        }
        __syncthreads();
        if (S.bcast * inv256 < TOLF) break;   // uniform across all CTAs
    }

    // ---- output: mean over dims of (y1 + y) per sample ----
    float o0 = y1r0 + yr0;
    float o1 = y1r1 + yr1;
    if (half == 0) {
#pragma unroll
        for (int o = 16; o; o >>= 1) {
            o0 += __shfl_xor_sync(0xffffffffu, o0, o);
            o1 += __shfl_xor_sync(0xffffffffu, o1, o);
        }
        if ((h & 31) == 0) { S.red[0][h >> 5] = o0;  S.red[1][h >> 5] = o1; }
    }
    __syncthreads();
    if (tid == 0) {
        out[samp]     = (S.red[0][0] + S.red[0][1] + S.red[0][2] + S.red[0][3]) * (1.f / 128.f);
        out[samp + 1] = (S.red[1][0] + S.red[1][1] + S.red[1][2] + S.red[1][3]) * (1.f / 128.f);
    }
}

extern "C" void kernel_launch(void* const* d_in, const int* in_sizes, int n_in,
                              void* d_out, int out_size) {
    (void)in_sizes; (void)n_in; (void)out_size;
    const float* x      = (const float*)d_in[0];
    const float* y      = (const float*)d_in[1];
    const float* wuu0_w = (const float*)d_in[2];
    const float* wuu0_b = (const float*)d_in[3];
    const float* wyu0_w = (const float*)d_in[4];
    const float* wyu0_b = (const float*)d_in[5];
    const float* wy0    = (const float*)d_in[6];
    const float* wu0_w  = (const float*)d_in[7];
    const float* wu0_b  = (const float*)d_in[8];
    const float* wuu1_w = (const float*)d_in[9];
    const float* wuu1_b = (const float*)d_in[10];
    const float* wzu1_w = (const float*)d_in[11];
    const float* wzu1_b = (const float*)d_in[12];
    const float* wz1    = (const float*)d_in[13];
    const float* wyu1_w = (const float*)d_in[14];
    const float* wyu1_b = (const float*)d_in[15];
    const float* wy1    = (const float*)d_in[16];
    const float* wu1_w  = (const float*)d_in[17];
    const float* wu1_b  = (const float*)d_in[18];
    const float* wzu2_w = (const float*)d_in[19];
    const float* wzu2_b = (const float*)d_in[20];
    const float* wz2    = (const float*)d_in[21];
    const float* wyu2_w = (const float*)d_in[22];
    const float* wyu2_b = (const float*)d_in[23];
    const float* wy2    = (const float*)d_in[24];
    // d_in[25] (wu2_w), d_in[26] (wu2_b) do not affect the gradient / output.

    size_t smem = sizeof(Smem);
    cudaFuncSetAttribute(pblnn_kernel, cudaFuncAttributeMaxDynamicSharedMemorySize, (int)smem);

    pblnn_init_kernel<<<2, 256>>>();
    pblnn_kernel<<<NCTA, NTHREADS, smem>>>(
        x, y,
        wuu0_w, wuu0_b, wyu0_w, wyu0_b, wy0, wu0_w, wu0_b,
        wuu1_w, wuu1_b, wzu1_w, wzu1_b, wz1, wyu1_w, wyu1_b, wy1, wu1_w, wu1_b,
        wzu2_w, wzu2_b, wz2, wyu2_w, wyu2_b, wy2,
        (float*)d_out);
}

// round 2
// speedup vs baseline: 2.0207x; 2.0207x over previous
#include <cuda_runtime.h>
#include <math.h>

#define H        128
#define STRIDE   132      // 132 % 32 == 4 -> conflict-free row AND column smem access
#define NCTA     128
#define NTHREADS 512
#define MAXIT    500
#define TOLF     1e-3f

__device__ unsigned g_count;          // grid-barrier arrival counter (zeroed per launch)
__device__ float    g_res[MAXIT];     // per-iteration residual accumulators

struct __align__(16) Smem {
    float Wy0[H * STRIDE];
    float Wy1[H * STRIDE];
    float W1p[H * STRIDE];
    float yv0[2][H];
    float yv1[2][H];
    float zz [2][H];
    float v2 [2][H];
    float v1 [2][H];
    float P1[4][2][STRIDE];   // [quarter][sample][h], padded inner
    float P2[4][2][STRIDE];
    float xbuf[2][H];
    float ubuf[2][H];
    float red[8];
    int   flag;
};

__global__ void pblnn_init_kernel() {
    int t = blockIdx.x * blockDim.x + threadIdx.x;
    if (t == 0) g_count = 0u;
    if (t < MAXIT) g_res[t] = 0.f;
}

__device__ __forceinline__ float softplus_f(float s) {
    float e = __expf(s);
    float z = __logf(1.f + e);
    return (s > 15.f) ? s : z;
}

__device__ __forceinline__ void spsig(float s, float& z, float& sg) {
    float e = __expf(s);
    float zz_ = __logf(1.f + e);
    float sgg = e / (1.f + e);
    if (s > 15.f) { zz_ = s; sgg = 1.f; }
    z = zz_; sg = sgg;
}

// single-sample dot: smem vector (128) . gmem row (128), float4 loads
__device__ __forceinline__ float dot1(const float* xs, const float* __restrict__ w) {
    float a = 0.f, b = 0.f;
#pragma unroll
    for (int j = 0; j < H; j += 8) {
        float4 wv0 = __ldg((const float4*)&w[j]);
        float4 wv1 = __ldg((const float4*)&w[j + 4]);
        float4 u0 = *(const float4*)&xs[j];
        float4 u1 = *(const float4*)&xs[j + 4];
        a += wv0.x * u0.x + wv0.y * u0.y + wv0.z * u0.z + wv0.w * u0.w;
        b += wv1.x * u1.x + wv1.y * u1.y + wv1.z * u1.z + wv1.w * u1.w;
    }
    return a + b;
}

__global__ __launch_bounds__(NTHREADS, 1)
void pblnn_kernel(
    const float* __restrict__ x,      const float* __restrict__ y,
    const float* __restrict__ wuu0_w, const float* __restrict__ wuu0_b,
    const float* __restrict__ wyu0_w, const float* __restrict__ wyu0_b,
    const float* __restrict__ wy0,
    const float* __restrict__ wu0_w,  const float* __restrict__ wu0_b,
    const float* __restrict__ wuu1_w, const float* __restrict__ wuu1_b,
    const float* __restrict__ wzu1_w, const float* __restrict__ wzu1_b,
    const float* __restrict__ wz1,
    const float* __restrict__ wyu1_w, const float* __restrict__ wyu1_b,
    const float* __restrict__ wy1,
    const float* __restrict__ wu1_w,  const float* __restrict__ wu1_b,
    const float* __restrict__ wzu2_w, const float* __restrict__ wzu2_b,
    const float* __restrict__ wz2,
    const float* __restrict__ wyu2_w, const float* __restrict__ wyu2_b,
    const float* __restrict__ wy2,
    float* __restrict__ out)
{
    extern __shared__ char smem_raw[];
    Smem& S = *reinterpret_cast<Smem*>(smem_raw);

    const int tid  = threadIdx.x;
    const int h    = tid & (H - 1);
    const int q    = tid >> 7;          // quarter 0..3
    const int k0   = q * 32;
    const bool act = (q < 2);           // active in elementwise segments; s = q
    const int s    = q & 1;
    const int samp = blockIdx.x * 2;

    // ---- stage x + weights into smem (float4, stride-132 padded) ----
    for (int e = tid; e < 2 * H; e += NTHREADS)
        S.xbuf[e >> 7][e & 127] = x[samp * H + e];
    for (int e = tid; e < H * H / 4; e += NTHREADS) {
        int r = e >> 5, c4 = (e & 31) * 4;
        *(float4*)&S.Wy0[r * STRIDE + c4] = __ldg((const float4*)&wy0[r * H + c4]);
        *(float4*)&S.Wy1[r * STRIDE + c4] = __ldg((const float4*)&wy1[r * H + c4]);
        float4 wv = __ldg((const float4*)&wz1[r * H + c4]);
        wv.x = fmaxf(wv.x, 0.f); wv.y = fmaxf(wv.y, 0.f);
        wv.z = fmaxf(wv.z, 0.f); wv.w = fmaxf(wv.w, 0.f);
        *(float4*)&S.W1p[r * STRIDE + c4] = wv;
    }
    __syncthreads();

    // ---- register-cache M2 row segments (W1p[h][k0..k0+32), Wy1[h][...]) ----
    float cw1[32], cwy[32];
#pragma unroll
    for (int i = 0; i < 32; i++) {
        cw1[i] = S.W1p[h * STRIDE + k0 + i];
        cwy[i] = S.Wy1[h * STRIDE + k0 + i];
    }

    // ---- y-independent precompute (one-time; act threads, one sample each) ----
    float a0r = 0.f, a1r = 0.f, c0r = 0.f, c1r = 0.f, zur = 0.f;
    float vw2 = 0.f, a2w = 0.f, yr = 0.f, y1r = 1.f, zs1r = 0.f, gAr = 0.f;

    if (act) {
        const float* xs = S.xbuf[s];
        float u0 = softplus_f(dot1(xs, &wuu0_w[h * H]) + wuu0_b[h]);
        a0r = dot1(xs, &wyu0_w[h * H]) + wyu0_b[h];
        c0r = dot1(xs, &wu0_w[h * H]) + wu0_b[h];
        S.ubuf[s][h] = u0;
    }
    __syncthreads();
    float u1 = 0.f;
    if (act) {
        const float* us = S.ubuf[s];
        u1  = softplus_f(dot1(us, &wuu1_w[h * H]) + wuu1_b[h]);
        zur = softplus_f(dot1(us, &wzu1_w[h * H]) + wzu1_b[h]);
        a1r = dot1(us, &wyu1_w[h * H]) + wyu1_b[h];
        c1r = dot1(us, &wu1_w[h * H]) + wu1_b[h];
    }
    __syncthreads();
    if (act) S.ubuf[s][h] = u1;
    __syncthreads();
    if (act) {
        const float* us = S.ubuf[s];
        a2w = (dot1(us, &wyu2_w[h * H]) + wyu2_b[h]) * wy2[h];
        float zu2 = softplus_f(dot1(us, wzu2_w) + wzu2_b[0]);
        vw2 = zu2 * fmaxf(wz2[h], 0.f);
        yr = y[(samp + s) * H + h];
    }

    // ---- fixed-point iterations (deferred/pipelined convergence check) ----
    for (int it = 0; it < MAXIT; ++it) {
        if (act) {
            S.yv0[s][h] = y1r * a0r;
            S.yv1[s][h] = y1r * a1r;
        }
        __syncthreads();                                   // #1

        // checker thread overlaps the grid-sync wait with the whole iteration
        if (tid == 384) {
            int f = 0;
            if (it > 0) {
                unsigned tgt = (unsigned)it * (unsigned)NCTA;
                while (*((volatile unsigned*)&g_count) < tgt) { }
                __threadfence();
                if (*((volatile float*)&g_res[it - 1]) * (1.f / 256.f) < TOLF) f = 1;
            }
            S.flag = f;
        }

        // M1: s1 partial over j in [k0,k0+32)
        {
            const float4* W  = (const float4*)&S.Wy0[h * STRIDE + k0];
            const float4* V0 = (const float4*)&S.yv0[0][k0];
            const float4* V1 = (const float4*)&S.yv0[1][k0];
            float m0 = 0.f, m1 = 0.f;
#pragma unroll
            for (int c = 0; c < 8; c++) {
                float4 w = W[c], a = V0[c], b = V1[c];
                m0 += w.x * a.x + w.y * a.y + w.z * a.z + w.w * a.w;
                m1 += w.x * b.x + w.y * b.y + w.z * b.z + w.w * b.w;
            }
            S.P1[q][0][h] = m0;  S.P1[q][1][h] = m1;
        }
        __syncthreads();                                   // #2

        if (act) {
            float s1 = S.P1[0][s][h] + S.P1[1][s][h] + S.P1[2][s][h] + S.P1[3][s][h] + c0r;
            float z1, sg1;
            spsig(s1, z1, sg1);
            zs1r = sg1 * zur;
            S.zz[s][h] = z1 * zur;
        }
        __syncthreads();                                   // #3

        // M2: s2 partial, weights from registers
        {
            const float4* Z0 = (const float4*)&S.zz[0][k0];
            const float4* Z1 = (const float4*)&S.zz[1][k0];
            const float4* Y0 = (const float4*)&S.yv1[0][k0];
            const float4* Y1 = (const float4*)&S.yv1[1][k0];
            float m0 = 0.f, m1 = 0.f;
#pragma unroll
            for (int c = 0; c < 8; c++) {
                float4 z0 = Z0[c], z1v = Z1[c], u0v = Y0[c], u1v = Y1[c];
                m0 += cw1[4*c+0] * z0.x + cw1[4*c+1] * z0.y + cw1[4*c+2] * z0.z + cw1[4*c+3] * z0.w
                    + cwy[4*c+0] * u0v.x + cwy[4*c+1] * u0v.y + cwy[4*c+2] * u0v.z + cwy[4*c+3] * u0v.w;
                m1 += cw1[4*c+0] * z1v.x + cw1[4*c+1] * z1v.y + cw1[4*c+2] * z1v.z + cw1[4*c+3] * z1v.w
                    + cwy[4*c+0] * u1v.x + cwy[4*c+1] * u1v.y + cwy[4*c+2] * u1v.z + cwy[4*c+3] * u1v.w;
            }
            S.P1[q][0][h] = m0;  S.P1[q][1][h] = m1;
        }
        __syncthreads();                                   // #4

        if (act) {
            float s2 = S.P1[0][s][h] + S.P1[1][s][h] + S.P1[2][s][h] + S.P1[3][s][h] + c1r;
            float sg2 = 1.f / (1.f + __expf(-s2));
            S.v2[s][h] = vw2 * sg2;
        }
        __syncthreads();                                   // #5

        // C: tv partial (W1p cols) + gA partial (Wy1 cols) fused
        {
            float tA0 = 0.f, tA1 = 0.f, gA0 = 0.f, gA1 = 0.f;
#pragma unroll
            for (int c = 0; c < 8; c++) {
                int kp = k0 + 4 * c;
                float4 a = *(const float4*)&S.v2[0][kp];
                float4 b = *(const float4*)&S.v2[1][kp];
#define STC(r, av, bv) { \
                float wA = S.W1p[(kp + r) * STRIDE + h]; \
                float wB = S.Wy1[(kp + r) * STRIDE + h]; \
                tA0 += (av) * wA;  tA1 += (bv) * wA; \
                gA0 += (av) * wB;  gA1 += (bv) * wB; }
                STC(0, a.x, b.x) STC(1, a.y, b.y) STC(2, a.z, b.z) STC(3, a.w, b.w)
#undef STC
            }
            S.P1[q][0][h] = tA0;  S.P1[q][1][h] = tA1;
            S.P2[q][0][h] = gA0;  S.P2[q][1][h] = gA1;
        }
        __syncthreads();                                   // #6

        if (act) {
            float tv = S.P1[0][s][h] + S.P1[1][s][h] + S.P1[2][s][h] + S.P1[3][s][h];
            gAr      = S.P2[0][s][h] + S.P2[1][s][h] + S.P2[2][s][h] + S.P2[3][s][h];
            S.v1[s][h] = tv * zs1r;
        }
        __syncthreads();                                   // #7

        // D: gB partial (Wy0 cols)
        {
            float g0 = 0.f, g1 = 0.f;
#pragma unroll
            for (int c = 0; c < 8; c++) {
                int kp = k0 + 4 * c;
                float4 a = *(const float4*)&S.v1[0][kp];
                float4 b = *(const float4*)&S.v1[1][kp];
#define STD(r, av, bv) { \
                float w = S.Wy0[(kp + r) * STRIDE + h]; \
                g0 += (av) * w;  g1 += (bv) * w; }
                STD(0, a.x, b.x) STD(1, a.y, b.y) STD(2, a.z, b.z) STD(3, a.w, b.w)
#undef STD
            }
            S.P1[q][0][h] = g0;  S.P1[q][1][h] = g1;
        }
        __syncthreads();                                   // #8

        float rres = 0.f;
        if (act) {
            float gB = S.P1[0][s][h] + S.P1[1][s][h] + S.P1[2][s][h] + S.P1[3][s][h];
            float g = a1r * gAr + a0r * gB + a2w + 0.5f * y1r;
            rres = yr - g;
            float qq = rres * rres;
#pragma unroll
            for (int o = 16; o; o >>= 1)
                qq += __shfl_xor_sync(0xffffffffu, qq, o);
            if ((h & 31) == 0) S.red[tid >> 5] = qq;   // warps 0..7
        }
        __syncthreads();                                   // #9

        if (S.flag) break;        // converged at iteration it-1 -> freeze (y1 pre-update)

        if (act) y1r += (4.f / (float)(it + 1)) * rres;

        if (tid == 0) {
            float n0 = sqrtf(S.red[0] + S.red[1] + S.red[2] + S.red[3]);
            float n1 = sqrtf(S.red[4] + S.red[5] + S.red[6] + S.red[7]);
            atomicAdd(&g_res[it], n0 + n1);
            __threadfence();
            atomicAdd(&g_count, 1u);
        }
    }

    // ---- output: mean over dims of (y1 + y) per sample ----
    if (act) {
        float o = y1r + yr;
#pragma unroll
        for (int off = 16; off; off >>= 1)
            o += __shfl_xor_sync(0xffffffffu, o, off);
        if ((h & 31) == 0) S.red[tid >> 5] = o;
    }
    __syncthreads();
    if (tid == 0) {
        out[samp]     = (S.red[0] + S.red[1] + S.red[2] + S.red[3]) * (1.f / 128.f);
        out[samp + 1] = (S.red[4] + S.red[5] + S.red[6] + S.red[7]) * (1.f / 128.f);
    }
}

extern "C" void kernel_launch(void* const* d_in, const int* in_sizes, int n_in,
                              void* d_out, int out_size) {
    (void)in_sizes; (void)n_in; (void)out_size;
    const float* x      = (const float*)d_in[0];
    const float* y      = (const float*)d_in[1];
    const float* wuu0_w = (const float*)d_in[2];
    const float* wuu0_b = (const float*)d_in[3];
    const float* wyu0_w = (const float*)d_in[4];
    const float* wyu0_b = (const float*)d_in[5];
    const float* wy0    = (const float*)d_in[6];
    const float* wu0_w  = (const float*)d_in[7];
    const float* wu0_b  = (const float*)d_in[8];
    const float* wuu1_w = (const float*)d_in[9];
    const float* wuu1_b = (const float*)d_in[10];
    const float* wzu1_w = (const float*)d_in[11];
    const float* wzu1_b = (const float*)d_in[12];
    const float* wz1    = (const float*)d_in[13];
    const float* wyu1_w = (const float*)d_in[14];
    const float* wyu1_b = (const float*)d_in[15];
    const float* wy1    = (const float*)d_in[16];
    const float* wu1_w  = (const float*)d_in[17];
    const float* wu1_b  = (const float*)d_in[18];
    const float* wzu2_w = (const float*)d_in[19];
    const float* wzu2_b = (const float*)d_in[20];
    const float* wz2    = (const float*)d_in[21];
    const float* wyu2_w = (const float*)d_in[22];
    const float* wyu2_b = (const float*)d_in[23];
    const float* wy2    = (const float*)d_in[24];
    // d_in[25] (wu2_w), d_in[26] (wu2_b) do not affect the gradient / output.

    size_t smem = sizeof(Smem);
    cudaFuncSetAttribute(pblnn_kernel, cudaFuncAttributeMaxDynamicSharedMemorySize, (int)smem);

    pblnn_init_kernel<<<2, 256>>>();
    pblnn_kernel<<<NCTA, NTHREADS, smem>>>(
        x, y,
        wuu0_w, wuu0_b, wyu0_w, wyu0_b, wy0, wu0_w, wu0_b,
        wuu1_w, wuu1_b, wzu1_w, wzu1_b, wz1, wyu1_w, wyu1_b, wy1, wu1_w, wu1_b,
        wzu2_w, wzu2_b, wz2, wyu2_w, wyu2_b, wy2,
        (float*)d_out);
}

// round 3
// speedup vs baseline: 2.0263x; 1.0028x over previous
#include <cuda_runtime.h>
#include <math.h>

#define H        128
#define STRIDE   132      // 132 % 32 == 4 -> conflict-free row AND column smem access
#define NCTA     128
#define NTHREADS 512
#define MAXIT    500
#define TOLF     1e-3f

__device__ unsigned g_count;          // grid-barrier arrival counter (zeroed per launch)
__device__ float    g_res[MAXIT];     // per-iteration residual accumulators

struct __align__(16) Smem {
    float Wy0[H * STRIDE];
    float Wy1[H * STRIDE];
    float W1p[H * STRIDE];
    float yv0[2][H];
    float yv1[2][H];
    float zz [2][H];
    float v2 [2][H];
    float v1 [2][H];
    float P1[4][2][STRIDE];   // [quarter][sample][h], padded inner
    float P2[4][2][STRIDE];
    float xbuf[2][H];
    float ubuf[2][H];
    float red[8];
    int   flag;
};

__global__ void pblnn_init_kernel() {
    int t = blockIdx.x * blockDim.x + threadIdx.x;
    if (t == 0) g_count = 0u;
    if (t < MAXIT) g_res[t] = 0.f;
}

__device__ __forceinline__ float softplus_f(float s) {
    float e = __expf(s);
    float z = __logf(1.f + e);
    return (s > 15.f) ? s : z;
}

__device__ __forceinline__ void spsig(float s, float& z, float& sg) {
    float e = __expf(s);
    float zz_ = __logf(1.f + e);
    float sgg = e / (1.f + e);
    if (s > 15.f) { zz_ = s; sgg = 1.f; }
    z = zz_; sg = sgg;
}

// single-sample dot: smem vector (128) . gmem row (128), float4 loads
__device__ __forceinline__ float dot1(const float* xs, const float* __restrict__ w) {
    float a = 0.f, b = 0.f;
#pragma unroll
    for (int j = 0; j < H; j += 8) {
        float4 wv0 = __ldg((const float4*)&w[j]);
        float4 wv1 = __ldg((const float4*)&w[j + 4]);
        float4 u0 = *(const float4*)&xs[j];
        float4 u1 = *(const float4*)&xs[j + 4];
        a += wv0.x * u0.x + wv0.y * u0.y + wv0.z * u0.z + wv0.w * u0.w;
        b += wv1.x * u1.x + wv1.y * u1.y + wv1.z * u1.z + wv1.w * u1.w;
    }
    return a + b;
}

__global__ __launch_bounds__(NTHREADS, 1)
void pblnn_kernel(
    const float* __restrict__ x,      const float* __restrict__ y,
    const float* __restrict__ wuu0_w, const float* __restrict__ wuu0_b,
    const float* __restrict__ wyu0_w, const float* __restrict__ wyu0_b,
    const float* __restrict__ wy0,
    const float* __restrict__ wu0_w,  const float* __restrict__ wu0_b,
    const float* __restrict__ wuu1_w, const float* __restrict__ wuu1_b,
    const float* __restrict__ wzu1_w, const float* __restrict__ wzu1_b,
    const float* __restrict__ wz1,
    const float* __restrict__ wyu1_w, const float* __restrict__ wyu1_b,
    const float* __restrict__ wy1,
    const float* __restrict__ wu1_w,  const float* __restrict__ wu1_b,
    const float* __restrict__ wzu2_w, const float* __restrict__ wzu2_b,
    const float* __restrict__ wz2,
    const float* __restrict__ wyu2_w, const float* __restrict__ wyu2_b,
    const float* __restrict__ wy2,
    float* __restrict__ out)
{
    extern __shared__ char smem_raw[];
    Smem& S = *reinterpret_cast<Smem*>(smem_raw);

    const int tid  = threadIdx.x;
    const int h    = tid & (H - 1);
    const int q    = tid >> 7;          // quarter 0..3
    const int k0   = q * 32;
    const bool act = (q < 2);           // active in elementwise segments; s = q
    const int s    = q & 1;
    const int samp = blockIdx.x * 2;

    // ---- stage x + weights into smem (float4, stride-132 padded) ----
    for (int e = tid; e < 2 * H; e += NTHREADS)
        S.xbuf[e >> 7][e & 127] = x[samp * H + e];
    for (int e = tid; e < H * H / 4; e += NTHREADS) {
        int r = e >> 5, c4 = (e & 31) * 4;
        *(float4*)&S.Wy0[r * STRIDE + c4] = __ldg((const float4*)&wy0[r * H + c4]);
        *(float4*)&S.Wy1[r * STRIDE + c4] = __ldg((const float4*)&wy1[r * H + c4]);
        float4 wv = __ldg((const float4*)&wz1[r * H + c4]);
        wv.x = fmaxf(wv.x, 0.f); wv.y = fmaxf(wv.y, 0.f);
        wv.z = fmaxf(wv.z, 0.f); wv.w = fmaxf(wv.w, 0.f);
        *(float4*)&S.W1p[r * STRIDE + c4] = wv;
    }
    __syncthreads();

    // ---- register-cache M2 row segments (W1p[h][k0..k0+32), Wy1[h][...]) ----
    float cw1[32], cwy[32];
#pragma unroll
    for (int i = 0; i < 32; i++) {
        cw1[i] = S.W1p[h * STRIDE + k0 + i];
        cwy[i] = S.Wy1[h * STRIDE + k0 + i];
    }

    // ---- y-independent precompute (one-time; act threads, one sample each) ----
    float a0r = 0.f, a1r = 0.f, c0r = 0.f, c1r = 0.f, zur = 0.f;
    float vw2 = 0.f, a2w = 0.f, yr = 0.f, y1r = 1.f, zs1r = 0.f, gAr = 0.f;

    if (act) {
        const float* xs = S.xbuf[s];
        float u0 = softplus_f(dot1(xs, &wuu0_w[h * H]) + wuu0_b[h]);
        a0r = dot1(xs, &wyu0_w[h * H]) + wyu0_b[h];
        c0r = dot1(xs, &wu0_w[h * H]) + wu0_b[h];
        S.ubuf[s][h] = u0;
    }
    __syncthreads();
    float u1 = 0.f;
    if (act) {
        const float* us = S.ubuf[s];
        u1  = softplus_f(dot1(us, &wuu1_w[h * H]) + wuu1_b[h]);
        zur = softplus_f(dot1(us, &wzu1_w[h * H]) + wzu1_b[h]);
        a1r = dot1(us, &wyu1_w[h * H]) + wyu1_b[h];
        c1r = dot1(us, &wu1_w[h * H]) + wu1_b[h];
    }
    __syncthreads();
    if (act) S.ubuf[s][h] = u1;
    __syncthreads();
    if (act) {
        const float* us = S.ubuf[s];
        a2w = (dot1(us, &wyu2_w[h * H]) + wyu2_b[h]) * wy2[h];
        float zu2 = softplus_f(dot1(us, wzu2_w) + wzu2_b[0]);
        vw2 = zu2 * fmaxf(wz2[h], 0.f);
        yr = y[(samp + s) * H + h];
    }

    // ---- fixed-point iterations (deferred/pipelined convergence check) ----
    for (int it = 0; it < MAXIT; ++it) {
        if (act) {
            S.yv0[s][h] = y1r * a0r;
            S.yv1[s][h] = y1r * a1r;
        }
        __syncthreads();                                   // #1

        // checker thread overlaps the grid-sync wait with the whole iteration
        if (tid == 384) {
            int f = 0;
            if (it > 0) {
                unsigned tgt = (unsigned)it * (unsigned)NCTA;
                while (*((volatile unsigned*)&g_count) < tgt) { }
                __threadfence();
                if (*((volatile float*)&g_res[it - 1]) * (1.f / 256.f) < TOLF) f = 1;
            }
            S.flag = f;
        }

        // M1: s1 partial over j in [k0,k0+32)
        {
            const float4* W  = (const float4*)&S.Wy0[h * STRIDE + k0];
            const float4* V0 = (const float4*)&S.yv0[0][k0];
            const float4* V1 = (const float4*)&S.yv0[1][k0];
            float m0 = 0.f, m1 = 0.f;
#pragma unroll
            for (int c = 0; c < 8; c++) {
                float4 w = W[c], a = V0[c], b = V1[c];
                m0 += w.x * a.x + w.y * a.y + w.z * a.z + w.w * a.w;
                m1 += w.x * b.x + w.y * b.y + w.z * b.z + w.w * b.w;
            }
            S.P1[q][0][h] = m0;  S.P1[q][1][h] = m1;
        }
        __syncthreads();                                   // #2

        if (act) {
            float s1 = S.P1[0][s][h] + S.P1[1][s][h] + S.P1[2][s][h] + S.P1[3][s][h] + c0r;
            float z1, sg1;
            spsig(s1, z1, sg1);
            zs1r = sg1 * zur;
            S.zz[s][h] = z1 * zur;
        }
        __syncthreads();                                   // #3

        // M2: s2 partial, weights from registers
        {
            const float4* Z0 = (const float4*)&S.zz[0][k0];
            const float4* Z1 = (const float4*)&S.zz[1][k0];
            const float4* Y0 = (const float4*)&S.yv1[0][k0];
            const float4* Y1 = (const float4*)&S.yv1[1][k0];
            float m0 = 0.f, m1 = 0.f;
#pragma unroll
            for (int c = 0; c < 8; c++) {
                float4 z0 = Z0[c], z1v = Z1[c], u0v = Y0[c], u1v = Y1[c];
                m0 += cw1[4*c+0] * z0.x + cw1[4*c+1] * z0.y + cw1[4*c+2] * z0.z + cw1[4*c+3] * z0.w
                    + cwy[4*c+0] * u0v.x + cwy[4*c+1] * u0v.y + cwy[4*c+2] * u0v.z + cwy[4*c+3] * u0v.w;
                m1 += cw1[4*c+0] * z1v.x + cw1[4*c+1] * z1v.y + cw1[4*c+2] * z1v.z + cw1[4*c+3] * z1v.w
                    + cwy[4*c+0] * u1v.x + cwy[4*c+1] * u1v.y + cwy[4*c+2] * u1v.z + cwy[4*c+3] * u1v.w;
            }
            S.P1[q][0][h] = m0;  S.P1[q][1][h] = m1;
        }
        __syncthreads();                                   // #4

        if (act) {
            float s2 = S.P1[0][s][h] + S.P1[1][s][h] + S.P1[2][s][h] + S.P1[3][s][h] + c1r;
            float sg2 = 1.f / (1.f + __expf(-s2));
            S.v2[s][h] = vw2 * sg2;
        }
        __syncthreads();                                   // #5

        // C: tv partial (W1p cols) + gA partial (Wy1 cols) fused
        {
            float tA0 = 0.f, tA1 = 0.f, gA0 = 0.f, gA1 = 0.f;
#pragma unroll
            for (int c = 0; c < 8; c++) {
                int kp = k0 + 4 * c;
                float4 a = *(const float4*)&S.v2[0][kp];
                float4 b = *(const float4*)&S.v2[1][kp];
#define STC(r, av, bv) { \
                float wA = S.W1p[(kp + r) * STRIDE + h]; \
                float wB = S.Wy1[(kp + r) * STRIDE + h]; \
                tA0 += (av) * wA;  tA1 += (bv) * wA; \
                gA0 += (av) * wB;  gA1 += (bv) * wB; }
                STC(0, a.x, b.x) STC(1, a.y, b.y) STC(2, a.z, b.z) STC(3, a.w, b.w)
#undef STC
            }
            S.P1[q][0][h] = tA0;  S.P1[q][1][h] = tA1;
            S.P2[q][0][h] = gA0;  S.P2[q][1][h] = gA1;
        }
        __syncthreads();                                   // #6

        if (act) {
            float tv = S.P1[0][s][h] + S.P1[1][s][h] + S.P1[2][s][h] + S.P1[3][s][h];
            gAr      = S.P2[0][s][h] + S.P2[1][s][h] + S.P2[2][s][h] + S.P2[3][s][h];
            S.v1[s][h] = tv * zs1r;
        }
        __syncthreads();                                   // #7

        // D: gB partial (Wy0 cols)
        {
            float g0 = 0.f, g1 = 0.f;
#pragma unroll
            for (int c = 0; c < 8; c++) {
                int kp = k0 + 4 * c;
                float4 a = *(const float4*)&S.v1[0][kp];
                float4 b = *(const float4*)&S.v1[1][kp];
#define STD(r, av, bv) { \
                float w = S.Wy0[(kp + r) * STRIDE + h]; \
                g0 += (av) * w;  g1 += (bv) * w; }
                STD(0, a.x, b.x) STD(1, a.y, b.y) STD(2, a.z, b.z) STD(3, a.w, b.w)
#undef STD
            }
            S.P1[q][0][h] = g0;  S.P1[q][1][h] = g1;
        }
        __syncthreads();                                   // #8

        float rres = 0.f;
        if (act) {
            float gB = S.P1[0][s][h] + S.P1[1][s][h] + S.P1[2][s][h] + S.P1[3][s][h];
            float g = a1r * gAr + a0r * gB + a2w + 0.5f * y1r;
            rres = yr - g;
            float qq = rres * rres;
#pragma unroll
            for (int o = 16; o; o >>= 1)
                qq += __shfl_xor_sync(0xffffffffu, qq, o);
            if ((h & 31) == 0) S.red[tid >> 5] = qq;   // warps 0..7
        }
        __syncthreads();                                   // #9

        if (S.flag) break;        // converged at iteration it-1 -> freeze (y1 pre-update)

        if (act) y1r += (4.f / (float)(it + 1)) * rres;

        if (tid == 0) {
            float n0 = sqrtf(S.red[0] + S.red[1] + S.red[2] + S.red[3]);
            float n1 = sqrtf(S.red[4] + S.red[5] + S.red[6] + S.red[7]);
            atomicAdd(&g_res[it], n0 + n1);
            __threadfence();
            atomicAdd(&g_count, 1u);
        }
    }

    // ---- output: mean over dims of (y1 + y) per sample ----
    if (act) {
        float o = y1r + yr;
#pragma unroll
        for (int off = 16; off; off >>= 1)
            o += __shfl_xor_sync(0xffffffffu, o, off);
        if ((h & 31) == 0) S.red[tid >> 5] = o;
    }
    __syncthreads();
    if (tid == 0) {
        out[samp]     = (S.red[0] + S.red[1] + S.red[2] + S.red[3]) * (1.f / 128.f);
        out[samp + 1] = (S.red[4] + S.red[5] + S.red[6] + S.red[7]) * (1.f / 128.f);
    }
}

extern "C" void kernel_launch(void* const* d_in, const int* in_sizes, int n_in,
                              void* d_out, int out_size) {
    (void)in_sizes; (void)n_in; (void)out_size;
    const float* x      = (const float*)d_in[0];
    const float* y      = (const float*)d_in[1];
    const float* wuu0_w = (const float*)d_in[2];
    const float* wuu0_b = (const float*)d_in[3];
    const float* wyu0_w = (const float*)d_in[4];
    const float* wyu0_b = (const float*)d_in[5];
    const float* wy0    = (const float*)d_in[6];
    const float* wu0_w  = (const float*)d_in[7];
    const float* wu0_b  = (const float*)d_in[8];
    const float* wuu1_w = (const float*)d_in[9];
    const float* wuu1_b = (const float*)d_in[10];
    const float* wzu1_w = (const float*)d_in[11];
    const float* wzu1_b = (const float*)d_in[12];
    const float* wz1    = (const float*)d_in[13];
    const float* wyu1_w = (const float*)d_in[14];
    const float* wyu1_b = (const float*)d_in[15];
    const float* wy1    = (const float*)d_in[16];
    const float* wu1_w  = (const float*)d_in[17];
    const float* wu1_b  = (const float*)d_in[18];
    const float* wzu2_w = (const float*)d_in[19];
    const float* wzu2_b = (const float*)d_in[20];
    const float* wz2    = (const float*)d_in[21];
    const float* wyu2_w = (const float*)d_in[22];
    const float* wyu2_b = (const float*)d_in[23];
    const float* wy2    = (const float*)d_in[24];
    // d_in[25] (wu2_w), d_in[26] (wu2_b) do not affect the gradient / output.

    size_t smem = sizeof(Smem);
    cudaFuncSetAttribute(pblnn_kernel, cudaFuncAttributeMaxDynamicSharedMemorySize, (int)smem);

    pblnn_init_kernel<<<2, 256>>>();
    pblnn_kernel<<<NCTA, NTHREADS, smem>>>(
        x, y,
        wuu0_w, wuu0_b, wyu0_w, wyu0_b, wy0, wu0_w, wu0_b,
        wuu1_w, wuu1_b, wzu1_w, wzu1_b, wz1, wyu1_w, wyu1_b, wy1, wu1_w, wu1_b,
        wzu2_w, wzu2_b, wz2, wyu2_w, wyu2_b, wy2,
        (float*)d_out);
}